// round 2
// baseline (speedup 1.0000x reference)
#include <cuda_runtime.h>
#include <cstdint>

// Problem shape
#define NB  16
#define NL  2048
#define NH  768
#define ND  64
#define CK  128           // chunk length
#define NCH (NL/CK)       // 16 chunks
#define HT  128           // h-tile
#define NHT (NH/HT)       // 6 h-tiles
#define DH  (ND*NH)       // 49152

typedef unsigned long long ull;

union F2U { ull u; float2 f; };

// packed dual-fp32 FMA: d.lo += a.lo*b.lo ; d.hi += a.hi*b.hi  (SASS FFMA2)
__device__ __forceinline__ void ffma2(ull &d, ull a, ull b) {
    asm("fma.rn.f32x2 %0, %1, %2, %0;" : "+l"(d) : "l"(a), "l"(b));
}

// Scratch (static device arrays — no allocation)
__device__ float g_E [NB*NL*ND];            // gathered embeddings            8.4 MB
__device__ float g_Fp[NB*NL*ND];            // (l+1) * (E @ w)                8.4 MB
__device__ float g_M [NB*NCH*ND*NH];        // chunk outer products -> excl. prefix  50 MB
__device__ float g_S [NB*NCH*CK*CK];        // masked intra-chunk scores      16.8 MB

// ---------------------------------------------------------------------------
// K0: embedding gather + Fp = (l+1) * E @ w
// ---------------------------------------------------------------------------
__global__ void k_embed(const void* __restrict__ xraw,
                        const float* __restrict__ ae,
                        const float* __restrict__ w)
{
    __shared__ float sW[ND][ND];
    __shared__ float sE[4][ND];

    int tid = threadIdx.x;

    // Detect index dtype: int64 (odd 32-bit words all zero) vs int32.
    const int* xi = (const int*)xraw;
    int oddw = xi[((tid & 63) << 1) + 1];
    int is64 = __syncthreads_and(oddw == 0);

    for (int i = tid; i < ND * ND; i += 256)
        ((float*)sW)[i] = w[i];

    int q = tid >> 6;
    int d = tid & 63;
    int t = blockIdx.x * 4 + q;
    int l = t & (NL - 1);

    long long v;
    if (is64) v = ((const long long*)xraw)[t];
    else      v = (long long)xi[t];

    float e = ae[v * ND + d];
    sE[q][d] = e;
    g_E[(size_t)t * ND + d] = e;
    __syncthreads();

    float acc = 0.f;
    #pragma unroll
    for (int k = 0; k < ND; k++)
        acc += sE[q][k] * sW[k][d];

    g_Fp[(size_t)t * ND + d] = (float)(l + 1) * acc;
}

// ---------------------------------------------------------------------------
// Shared loaders
// ---------------------------------------------------------------------------

// [128 rows x 32 cols] global slice (row stride gstride) TRANSPOSED -> st[32][128]
__device__ __forceinline__ void loadT_128x32(const float* __restrict__ g, int gstride,
                                             float (*st)[CK], int tid)
{
    int f4 = tid & 7;
    int r0 = tid >> 3;
    #pragma unroll
    for (int rep = 0; rep < 4; rep++) {
        int row = r0 + rep * 32;
        float4 v = *(const float4*)(g + (size_t)row * gstride + f4 * 4);
        st[f4*4 + 0][row] = v.x;
        st[f4*4 + 1][row] = v.y;
        st[f4*4 + 2][row] = v.z;
        st[f4*4 + 3][row] = v.w;
    }
}

// [32 rows x 128 cols] global slice -> DUPLICATED sbd[32][256] with XOR chunk
// swizzle (chunk = 16B group; phys = ch ^ (ch>>3)) for conflict-minimal STS.128.
__device__ __forceinline__ void loadB_dup(const float* __restrict__ g, int gstride,
                                          float (*sbd)[2*HT], int tid)
{
    int f4  = tid & 31;
    int row = tid >> 5;
    int ch0 = 2 * f4, ch1 = 2 * f4 + 1;
    int p0 = ch0 ^ (ch0 >> 3);
    int p1 = ch1 ^ (ch1 >> 3);
    #pragma unroll
    for (int rep = 0; rep < 4; rep++) {
        int r = row + rep * 8;
        float4 v = *(const float4*)(g + (size_t)r * gstride + f4 * 4);
        *(float4*)&sbd[r][p0 * 4] = make_float4(v.x, v.x, v.y, v.y);
        *(float4*)&sbd[r][p1 * 4] = make_float4(v.z, v.z, v.w, v.w);
    }
}

// [128 rows x 32 cols] global slice TRANSPOSED + DUPLICATED -> std_[32][256],
// same chunk swizzle as loadB_dup (read side is identical).
__device__ __forceinline__ void loadT_dup(const float* __restrict__ g, int gstride,
                                          float (*std_)[2*CK], int tid)
{
    int f4 = tid & 7;
    int r0 = tid >> 3;
    #pragma unroll
    for (int rep = 0; rep < 4; rep++) {
        int row = r0 + rep * 32;                 // logical dup-pair index
        int ch  = row >> 1;
        int pidx = ((ch ^ (ch >> 3)) << 2) + ((row & 1) * 2);
        float4 v = *(const float4*)(g + (size_t)row * gstride + f4 * 4);
        *(float2*)&std_[f4*4 + 0][pidx] = make_float2(v.x, v.x);
        *(float2*)&std_[f4*4 + 1][pidx] = make_float2(v.y, v.y);
        *(float2*)&std_[f4*4 + 2][pidx] = make_float2(v.z, v.z);
        *(float2*)&std_[f4*4 + 3][pidx] = make_float2(v.w, v.w);
    }
}

// Packed 32-deep micro-GEMM: acc[rp][s] (rp = j-pair, s = 0..7 B columns)
// A: transposed tile SA[32][128] (j contiguous -> natural f32x2 pairs)
// B: duplicated+swizzled tile SBD[32][256], chunks pch[0..3]
#define MMP32(SA, SBD) do {                                                  \
    _Pragma("unroll 8")                                                      \
    for (int kk = 0; kk < 32; kk++) {                                        \
        ulonglong2 aA = *(const ulonglong2*)&SA[kk][tj*8];                   \
        ulonglong2 aB = *(const ulonglong2*)&SA[kk][tj*8 + 4];               \
        ull av[4] = {aA.x, aA.y, aB.x, aB.y};                                \
        _Pragma("unroll")                                                    \
        for (int q = 0; q < 4; q++) {                                        \
            ulonglong2 bq = *(const ulonglong2*)&SBD[kk][pch[q] * 4];        \
            _Pragma("unroll")                                                \
            for (int rp = 0; rp < 4; rp++) {                                 \
                ffma2(acc[rp][2*q],     av[rp], bq.x);                       \
                ffma2(acc[rp][2*q + 1], av[rp], bq.y);                       \
            }                                                                \
        }                                                                    \
    }                                                                        \
} while (0)

// ---------------------------------------------------------------------------
// K1a: G[b][c] = Fp_c^T @ X_c   ([64 x C]@[C x H]) — packed along d
// ---------------------------------------------------------------------------
__global__ void k_outer(const float* __restrict__ bx)
{
    __shared__ float sF [32][ND];      //  8 KB  (natural [i][d])
    __shared__ float sXd[32][2*HT];    // 32 KB  (dup X)

    int tid = threadIdx.x;
    int ht = blockIdx.x, c = blockIdx.y, b = blockIdx.z;
    int h0 = ht * HT;

    const float* fpb = g_Fp + ((size_t)b * NL + c * CK) * ND;
    const float* xb  = bx   + ((size_t)b * NL + c * CK) * NH + h0;

    int td = tid & 15;       // d-quad
    int th = tid >> 4;       // h-oct
    int pch[4];
    #pragma unroll
    for (int q = 0; q < 4; q++) { int ch = 4*th + q; pch[q] = ch ^ (ch >> 3); }

    ull acc[2][8];
    #pragma unroll
    for (int r = 0; r < 2; r++)
        #pragma unroll
        for (int s = 0; s < 8; s++) acc[r][s] = 0ull;

    for (int it = 0; it < CK; it += 32) {
        {   // sF: 32x64 natural
            int f4 = tid & 15, row = tid >> 4;
            #pragma unroll
            for (int rep = 0; rep < 2; rep++) {
                float4 v = *(const float4*)(fpb + (size_t)(it + row + rep*16) * ND + f4 * 4);
                *(float4*)&sF[row + rep*16][f4 * 4] = v;
            }
        }
        loadB_dup(xb + (size_t)it * NH, NH, sXd, tid);
        __syncthreads();

        #pragma unroll 8
        for (int i = 0; i < 32; i++) {
            ulonglong2 aA = *(const ulonglong2*)&sF[i][td * 4];   // (d0,d1),(d2,d3)
            ull av[2] = {aA.x, aA.y};
            #pragma unroll
            for (int q = 0; q < 4; q++) {
                ulonglong2 bq = *(const ulonglong2*)&sXd[i][pch[q] * 4];
                #pragma unroll
                for (int rp = 0; rp < 2; rp++) {
                    ffma2(acc[rp][2*q],     av[rp], bq.x);
                    ffma2(acc[rp][2*q + 1], av[rp], bq.y);
                }
            }
        }
        __syncthreads();
    }

    float* gout = g_M + ((size_t)(b * NCH + c)) * DH + h0;
    #pragma unroll
    for (int rp = 0; rp < 2; rp++) {
        #pragma unroll
        for (int p = 0; p < 2; p++) {
            int d = td * 4 + rp * 2 + p;
            float* row = gout + (size_t)d * NH + th * 8;
            float v[8];
            #pragma unroll
            for (int s = 0; s < 8; s++) { F2U u; u.u = acc[rp][s]; v[s] = p ? u.f.y : u.f.x; }
            *(float4*)row       = make_float4(v[0], v[1], v[2], v[3]);
            *(float4*)(row + 4) = make_float4(v[4], v[5], v[6], v[7]);
        }
    }
}

// ---------------------------------------------------------------------------
// K1b: S[b][c][j][i] = E_c[j] . Fp_c[i], zeroed for i >= j — packed along j
// ---------------------------------------------------------------------------
__global__ void k_scores()
{
    __shared__ float sEt [32][CK];     // 16 KB  (transposed E: [d][j])
    __shared__ float sFtd[32][2*CK];   // 32 KB  (transposed+dup Fp: [d][dup i])

    int tid = threadIdx.x;
    int c = blockIdx.x, b = blockIdx.y;

    const float* Eb  = g_E  + ((size_t)b * NL + c * CK) * ND;
    const float* Fpb = g_Fp + ((size_t)b * NL + c * CK) * ND;

    int tj = tid & 15;      // j-oct
    int ti = tid >> 4;      // i-oct
    int pch[4];
    #pragma unroll
    for (int q = 0; q < 4; q++) { int ch = 4*ti + q; pch[q] = ch ^ (ch >> 3); }

    ull acc[4][8];
    #pragma unroll
    for (int r = 0; r < 4; r++)
        #pragma unroll
        for (int s = 0; s < 8; s++) acc[r][s] = 0ull;

    for (int dt = 0; dt < ND; dt += 32) {
        loadT_128x32(Eb + dt, ND, sEt, tid);
        loadT_dup  (Fpb + dt, ND, sFtd, tid);
        __syncthreads();
        MMP32(sEt, sFtd);
        __syncthreads();
    }

    float* Sout = g_S + ((size_t)(b * NCH + c)) * CK * CK;
    #pragma unroll
    for (int rp = 0; rp < 4; rp++) {
        #pragma unroll
        for (int p = 0; p < 2; p++) {
            int j = tj * 8 + rp * 2 + p;
            float* row = Sout + (size_t)j * CK + ti * 8;
            float v[8];
            #pragma unroll
            for (int s = 0; s < 8; s++) {
                F2U u; u.u = acc[rp][s];
                float val = p ? u.f.y : u.f.x;
                v[s] = (ti * 8 + s < j) ? val : 0.f;    // strict causal mask
            }
            *(float4*)row       = make_float4(v[0], v[1], v[2], v[3]);
            *(float4*)(row + 4) = make_float4(v[4], v[5], v[6], v[7]);
        }
    }
}

// ---------------------------------------------------------------------------
// K2: exclusive prefix over chunks, in place on g_M.
// ---------------------------------------------------------------------------
__global__ void k_prefix()
{
    int idx = blockIdx.x * 256 + threadIdx.x;
    int b  = idx / DH;
    int dh = idx - b * DH;
    float run = 0.f;
    size_t p = (size_t)b * NCH * DH + dh;
    #pragma unroll
    for (int c = 0; c < NCH; c++) {
        float v = g_M[p];
        g_M[p] = run;
        run += v;
        p += DH;
    }
}

// ---------------------------------------------------------------------------
// K3: out = X + diag(1/(j+1)) * ( E_c @ M_c  +  tril(S_c,-1) @ X_c )
// K = 192 in 32-deep slabs, packed along j
// ---------------------------------------------------------------------------
__global__ void k_final(const float* __restrict__ bx, float* __restrict__ out)
{
    __shared__ float sAt[32][CK];      // 16 KB  transposed A slab
    __shared__ float sBd[32][2*HT];    // 32 KB  dup B slab

    int tid = threadIdx.x;
    int ht = blockIdx.x, c = blockIdx.y, b = blockIdx.z;
    int h0 = ht * HT;

    int tj = tid & 15;      // j-oct
    int th = tid >> 4;      // h-oct
    int pch[4];
    #pragma unroll
    for (int q = 0; q < 4; q++) { int ch = 4*th + q; pch[q] = ch ^ (ch >> 3); }

    const float* Eb = g_E + ((size_t)b * NL + c * CK) * ND;
    const float* Mb = g_M + ((size_t)(b * NCH + c)) * DH + h0;
    const float* Sb = g_S + ((size_t)(b * NCH + c)) * CK * CK;
    const float* Xb = bx  + ((size_t)b * NL + c * CK) * NH + h0;

    ull acc[4][8];
    #pragma unroll
    for (int r = 0; r < 4; r++)
        #pragma unroll
        for (int s = 0; s < 8; s++) acc[r][s] = 0ull;

    // Inter-chunk: E_c @ M_c  (K = 64)
    for (int kt = 0; kt < 2; kt++) {
        loadT_128x32(Eb + kt * 32, ND, sAt, tid);
        loadB_dup(Mb + (size_t)(kt * 32) * NH, NH, sBd, tid);
        __syncthreads();
        MMP32(sAt, sBd);
        __syncthreads();
    }

    // Intra-chunk: tril(S) @ X_c  (K = 128; S pre-masked)
    for (int kt = 0; kt < 4; kt++) {
        loadT_128x32(Sb + kt * 32, CK, sAt, tid);
        loadB_dup(Xb + (size_t)(kt * 32) * NH, NH, sBd, tid);
        __syncthreads();
        MMP32(sAt, sBd);
        __syncthreads();
    }

    // Epilogue: out = x + (1/(j+1)) * acc
    float* ob = out + ((size_t)b * NL + c * CK) * NH + h0;
    #pragma unroll
    for (int rp = 0; rp < 4; rp++) {
        #pragma unroll
        for (int p = 0; p < 2; p++) {
            int j = tj * 8 + rp * 2 + p;
            float rj = 1.f / (float)(c * CK + j + 1);
            const float* xr = Xb + (size_t)j * NH + th * 8;
            float*     orow = ob + (size_t)j * NH + th * 8;
            float v[8];
            #pragma unroll
            for (int s = 0; s < 8; s++) { F2U u; u.u = acc[rp][s]; v[s] = p ? u.f.y : u.f.x; }
            float4 x0 = *(const float4*)xr;
            float4 x1 = *(const float4*)(xr + 4);
            *(float4*)orow       = make_float4(x0.x + rj * v[0], x0.y + rj * v[1],
                                               x0.z + rj * v[2], x0.w + rj * v[3]);
            *(float4*)(orow + 4) = make_float4(x1.x + rj * v[4], x1.y + rj * v[5],
                                               x1.z + rj * v[6], x1.w + rj * v[7]);
        }
    }
}

// ---------------------------------------------------------------------------
extern "C" void kernel_launch(void* const* d_in, const int* in_sizes, int n_in,
                              void* d_out, int out_size)
{
    const float* bx = (const float*)d_in[0];   // bert_x [B,L,H] f32
    const void*  x  = d_in[1];                 // x      [B,L]   int32/int64 (auto)
    const float* ae = (const float*)d_in[2];   // ae     [V,D]   f32
    const float* w  = (const float*)d_in[3];   // w      [D,D]   f32
    float* out = (float*)d_out;                // [B,L,H] f32

    (void)in_sizes; (void)n_in; (void)out_size;

    k_embed <<<NB * NL / 4, 256>>>(x, ae, w);
    k_outer <<<dim3(NHT, NCH, NB), 256>>>(bx);
    k_scores<<<dim3(NCH, NB), 256>>>();
    k_prefix<<<NB * DH / 256, 256>>>();
    k_final <<<dim3(NHT, NCH, NB), 256>>>(bx, out);
}

// round 4
// speedup vs baseline: 1.8250x; 1.8250x over previous
#include <cuda_runtime.h>
#include <cuda_bf16.h>
#include <cstdint>

// Problem shape
#define NB  16
#define NL  2048
#define NH  768
#define ND  64
#define CK  128
#define NCH (NL/CK)       // 16
#define HT  128
#define NHT (NH/HT)       // 6
#define DH  (ND*NH)       // 49152

typedef unsigned int u32;

// Scratch (static device arrays — no allocation)
__device__ float g_E [NB*NL*ND];       // gathered embeddings
__device__ float g_Fp[NB*NL*ND];       // (l+1)*(E@w)
__device__ float g_M [NB*NCH*DH];      // chunk outer products M[d][h] -> excl prefix
__device__ float g_S [NB*NCH*CK*CK];   // masked intra-chunk scores S[j][i]

// ---------------------------------------------------------------------------
// helpers
// ---------------------------------------------------------------------------
__device__ __forceinline__ u32 smem_u32(const void* p) {
    u32 a;
    asm("{ .reg .u64 t; cvta.to.shared.u64 t, %1; cvt.u32.u64 %0, t; }" : "=r"(a) : "l"(p));
    return a;
}
__device__ __forceinline__ u32 packbf(__nv_bfloat16 a, __nv_bfloat16 b) {
    __nv_bfloat162 t(a, b);
    return *reinterpret_cast<u32*>(&t);
}
// split two fp32 into hi/lo bf16x2 words
__device__ __forceinline__ void splitpack(float a, float b, u32& hi, u32& lo) {
    __nv_bfloat16 ah = __float2bfloat16(a);
    __nv_bfloat16 bh = __float2bfloat16(b);
    __nv_bfloat16 al = __float2bfloat16(a - __bfloat162float(ah));
    __nv_bfloat16 bl = __float2bfloat16(b - __bfloat162float(bh));
    hi = packbf(ah, bh);
    lo = packbf(al, bl);
}

__device__ __forceinline__ void ldsm4(u32* r, u32 addr) {
    asm volatile("ldmatrix.sync.aligned.m8n8.x4.shared.b16 {%0,%1,%2,%3}, [%4];"
        : "=r"(r[0]), "=r"(r[1]), "=r"(r[2]), "=r"(r[3]) : "r"(addr));
}
__device__ __forceinline__ void ldsm4t(u32* r, u32 addr) {
    asm volatile("ldmatrix.sync.aligned.m8n8.x4.trans.shared.b16 {%0,%1,%2,%3}, [%4];"
        : "=r"(r[0]), "=r"(r[1]), "=r"(r[2]), "=r"(r[3]) : "r"(addr));
}
__device__ __forceinline__ void mma16816(float* d, const u32* a, const u32* b) {
    asm volatile("mma.sync.aligned.m16n8k16.row.col.f32.bf16.bf16.f32 "
        "{%0,%1,%2,%3}, {%4,%5,%6,%7}, {%8,%9}, {%0,%1,%2,%3};"
        : "+f"(d[0]), "+f"(d[1]), "+f"(d[2]), "+f"(d[3])
        : "r"(a[0]), "r"(a[1]), "r"(a[2]), "r"(a[3]), "r"(b[0]), "r"(b[1]));
}

// ---------------------------------------------------------------------------
// smem tile loaders (fp32 global -> split bf16 hi/lo smem, XOR-swizzled)
//
// A-tile: [ROWS rows][64 k] bf16, 128B rows. chunk c (0..7, 16B = 8 bf16):
//   off = r*128 + ((c ^ (r&7)) << 4)
// B-tile: [64 rows][128 n] bf16, 256B rows. chunk c (0..15):
//   off = r*256 + ((c ^ (r&7)) << 4)
// ---------------------------------------------------------------------------
template<int ROWS>
__device__ __forceinline__ void loadA(char* sm, int offH, int offL,
                                      const float* __restrict__ g, int gs, int tid)
{
    #pragma unroll
    for (int it = 0; it < ROWS * 8 / 256; it++) {
        int idx = tid + it * 256;
        int r = idx >> 3, c = idx & 7;
        const float* p = g + (size_t)r * gs + c * 8;
        float4 v0 = *(const float4*)p;
        float4 v1 = *(const float4*)(p + 4);
        u32 h0,l0,h1,l1,h2,l2,h3,l3;
        splitpack(v0.x, v0.y, h0, l0);
        splitpack(v0.z, v0.w, h1, l1);
        splitpack(v1.x, v1.y, h2, l2);
        splitpack(v1.z, v1.w, h3, l3);
        int off = r * 128 + ((c ^ (r & 7)) << 4);
        *(uint4*)(sm + offH + off) = make_uint4(h0, h1, h2, h3);
        *(uint4*)(sm + offL + off) = make_uint4(l0, l1, l2, l3);
    }
}
__device__ __forceinline__ void loadB(char* sm, int offH, int offL,
                                      const float* __restrict__ g, int gs, int tid)
{
    #pragma unroll
    for (int it = 0; it < 4; it++) {
        int idx = tid + it * 256;
        int r = idx >> 4, c = idx & 15;
        const float* p = g + (size_t)r * gs + c * 8;
        float4 v0 = *(const float4*)p;
        float4 v1 = *(const float4*)(p + 4);
        u32 h0,l0,h1,l1,h2,l2,h3,l3;
        splitpack(v0.x, v0.y, h0, l0);
        splitpack(v0.z, v0.w, h1, l1);
        splitpack(v1.x, v1.y, h2, l2);
        splitpack(v1.z, v1.w, h3, l3);
        int off = r * 256 + ((c ^ (r & 7)) << 4);
        *(uint4*)(sm + offH + off) = make_uint4(h0, h1, h2, h3);
        *(uint4*)(sm + offL + off) = make_uint4(l0, l1, l2, l3);
    }
}

// ---------------------------------------------------------------------------
// K0: embedding gather + Fp = (l+1) * E @ w
// ---------------------------------------------------------------------------
__global__ void k_embed(const void* __restrict__ xraw,
                        const float* __restrict__ ae,
                        const float* __restrict__ w)
{
    __shared__ float sW[ND][ND];
    __shared__ float sE[4][ND];

    int tid = threadIdx.x;

    // Detect index dtype: int64 (odd 32-bit words all zero) vs int32.
    const int* xi = (const int*)xraw;
    int oddw = xi[((tid & 63) << 1) + 1];
    int is64 = __syncthreads_and(oddw == 0);

    for (int i = tid; i < ND * ND; i += 256)
        ((float*)sW)[i] = w[i];

    int q = tid >> 6;
    int d = tid & 63;
    int t = blockIdx.x * 4 + q;
    int l = t & (NL - 1);

    long long v;
    if (is64) v = ((const long long*)xraw)[t];
    else      v = (long long)xi[t];

    float e = ae[v * ND + d];
    sE[q][d] = e;
    g_E[(size_t)t * ND + d] = e;
    __syncthreads();

    float acc = 0.f;
    #pragma unroll
    for (int k = 0; k < ND; k++)
        acc += sE[q][k] * sW[k][d];

    g_Fp[(size_t)t * ND + d] = (float)(l + 1) * acc;
}

// ---------------------------------------------------------------------------
// K1b: intra-chunk scores S[j][i] = E[j].Fp[i], zero for i >= j (scalar fp32)
// ---------------------------------------------------------------------------
__global__ void k_scores()
{
    __shared__ float sEt[32][CK];
    __shared__ float sFt[32][CK];

    int tid = threadIdx.x;
    int c = blockIdx.x, b = blockIdx.y;

    const float* Eb  = g_E  + ((size_t)b * NL + c * CK) * ND;
    const float* Fpb = g_Fp + ((size_t)b * NL + c * CK) * ND;

    int tj = tid & 15;
    int ti = tid >> 4;

    float acc[8][8];
    #pragma unroll
    for (int r = 0; r < 8; r++)
        #pragma unroll
        for (int s = 0; s < 8; s++) acc[r][s] = 0.f;

    for (int dt = 0; dt < ND; dt += 32) {
        int f4 = tid & 7, r0 = tid >> 3;
        #pragma unroll
        for (int rep = 0; rep < 4; rep++) {
            int row = r0 + rep * 32;
            float4 v = *(const float4*)(Eb + (size_t)row * ND + dt + f4 * 4);
            sEt[f4*4+0][row] = v.x; sEt[f4*4+1][row] = v.y;
            sEt[f4*4+2][row] = v.z; sEt[f4*4+3][row] = v.w;
            float4 u = *(const float4*)(Fpb + (size_t)row * ND + dt + f4 * 4);
            sFt[f4*4+0][row] = u.x; sFt[f4*4+1][row] = u.y;
            sFt[f4*4+2][row] = u.z; sFt[f4*4+3][row] = u.w;
        }
        __syncthreads();

        #pragma unroll 8
        for (int kk = 0; kk < 32; kk++) {
            float4 a0 = *(const float4*)&sEt[kk][tj*8];
            float4 a1 = *(const float4*)&sEt[kk][tj*8 + 4];
            float4 b0 = *(const float4*)&sFt[kk][ti*8];
            float4 b1 = *(const float4*)&sFt[kk][ti*8 + 4];
            float av[8] = {a0.x,a0.y,a0.z,a0.w,a1.x,a1.y,a1.z,a1.w};
            float bv[8] = {b0.x,b0.y,b0.z,b0.w,b1.x,b1.y,b1.z,b1.w};
            #pragma unroll
            for (int r = 0; r < 8; r++)
                #pragma unroll
                for (int s = 0; s < 8; s++)
                    acc[r][s] += av[r] * bv[s];
        }
        __syncthreads();
    }

    float* Sout = g_S + (size_t)(b * NCH + c) * CK * CK;
    #pragma unroll
    for (int r = 0; r < 8; r++) {
        int j = tj * 8 + r;
        float* row = Sout + (size_t)j * CK + ti * 8;
        float v[8];
        #pragma unroll
        for (int s = 0; s < 8; s++)
            v[s] = (ti * 8 + s < j) ? acc[r][s] : 0.f;
        *(float4*)row       = make_float4(v[0], v[1], v[2], v[3]);
        *(float4*)(row + 4) = make_float4(v[4], v[5], v[6], v[7]);
    }
}

// ---------------------------------------------------------------------------
// K1a (mma): M[b][c][d][h] = sum_i Fp[i][d] * X[i][h]
// A = Fp (memory [k=i][m=d] -> ldmatrix.trans), B = X (memory [k=i][n=h] -> trans)
// CTA tile 64(d) x 128(h); warps 2x4, warp tile 32x32.  K=128, 2 slabs of 64.
// ---------------------------------------------------------------------------
#define KO_AH 0
#define KO_AL 8192
#define KO_BH 16384
#define KO_BL 32768
#define KO_TOT 49152

__global__ void __launch_bounds__(256, 1) k_outer_mma(const float* __restrict__ bx)
{
    extern __shared__ char sm[];
    u32 smb = smem_u32(sm);
    int tid = threadIdx.x, wid = tid >> 5, ln = tid & 31;
    int ht = blockIdx.x, c = blockIdx.y, b = blockIdx.z;
    int h0 = ht * HT;
    int mw = (wid >> 2) * 32;
    int nw = (wid & 3) * 32;

    const float* Fg = g_Fp + ((size_t)b * NL + c * CK) * ND;
    const float* Xg = bx   + ((size_t)b * NL + c * CK) * NH + h0;

    float acc[2][4][4];
    #pragma unroll
    for (int i = 0; i < 2; i++)
        #pragma unroll
        for (int j = 0; j < 4; j++)
            #pragma unroll
            for (int k = 0; k < 4; k++) acc[i][j][k] = 0.f;

    for (int slab = 0; slab < 2; slab++) {
        loadA<64>(sm, KO_AH, KO_AL, Fg + (size_t)slab * 64 * ND, ND, tid);
        loadB(sm, KO_BH, KO_BL, Xg + (size_t)slab * 64 * NH, NH, tid);
        __syncthreads();

        #pragma unroll
        for (int ks = 0; ks < 4; ks++) {
            u32 ah[2][4], al[2][4], bh[2][4], bl[2][4];
            int q = ln >> 3;
            #pragma unroll
            for (int mt = 0; mt < 2; mt++) {   // A via trans: rows=k, cols=m(d)
                int r = ks * 16 + (q >> 1) * 8 + (ln & 7);
                int mc = (mw + mt * 16 + (q & 1) * 8) >> 3;
                u32 off = r * 128 + ((mc ^ (r & 7)) << 4);
                ldsm4t(ah[mt], smb + KO_AH + off);
                ldsm4t(al[mt], smb + KO_AL + off);
            }
            #pragma unroll
            for (int nt2 = 0; nt2 < 2; nt2++) { // B via trans: rows=k, cols=n(h)
                int r = ks * 16 + (q & 1) * 8 + (ln & 7);
                int nc = (nw + nt2 * 16 + (q >> 1) * 8) >> 3;
                u32 off = r * 256 + ((nc ^ (r & 7)) << 4);
                ldsm4t(bh[nt2], smb + KO_BH + off);
                ldsm4t(bl[nt2], smb + KO_BL + off);
            }
            #pragma unroll
            for (int mt = 0; mt < 2; mt++)
                #pragma unroll
                for (int nt2 = 0; nt2 < 2; nt2++) {
                    mma16816(acc[mt][nt2*2],   ah[mt], &bh[nt2][0]);
                    mma16816(acc[mt][nt2*2+1], ah[mt], &bh[nt2][2]);
                    mma16816(acc[mt][nt2*2],   ah[mt], &bl[nt2][0]);
                    mma16816(acc[mt][nt2*2+1], ah[mt], &bl[nt2][2]);
                    mma16816(acc[mt][nt2*2],   al[mt], &bh[nt2][0]);
                    mma16816(acc[mt][nt2*2+1], al[mt], &bh[nt2][2]);
                }
        }
        __syncthreads();
    }

    float* Mo = g_M + (size_t)(b * NCH + c) * DH;
    #pragma unroll
    for (int mt = 0; mt < 2; mt++)
        #pragma unroll
        for (int half = 0; half < 2; half++) {
            int d = mw + mt * 16 + (ln >> 2) + half * 8;
            #pragma unroll
            for (int nt = 0; nt < 4; nt++) {
                int h = h0 + nw + nt * 8 + (ln & 3) * 2;
                *(float2*)(Mo + (size_t)d * NH + h) =
                    make_float2(acc[mt][nt][half*2], acc[mt][nt][half*2 + 1]);
            }
        }
}

// ---------------------------------------------------------------------------
// K2: exclusive prefix over chunks, in place on g_M (fp32)
// ---------------------------------------------------------------------------
__global__ void k_prefix()
{
    int idx = blockIdx.x * 256 + threadIdx.x;
    int b  = idx / DH;
    int dh = idx - b * DH;
    float run = 0.f;
    size_t p = (size_t)(b * NCH) * DH + dh;
    #pragma unroll
    for (int c = 0; c < NCH; c++) {
        float v = g_M[p];
        g_M[p] = run;
        run += v;
        p += DH;
    }
}

// ---------------------------------------------------------------------------
// K3 (mma): out[j][h] = X[j][h] + (1/(j+1)) * ( E@M + tril(S,-1)@X )
// A non-trans (E[j][d], S[j][i]); B trans (M[d][h], X[i][h]).
// CTA tile 128x128; warps 2x4, warp tile 64x32. K = 64 + 128 = 3 slabs of 64.
// ---------------------------------------------------------------------------
#define KF_AH 0
#define KF_AL 16384
#define KF_BH 32768
#define KF_BL 49152
#define KF_TOT 65536

__global__ void __launch_bounds__(256, 1) k_final_mma(const float* __restrict__ bx,
                                                      float* __restrict__ out)
{
    extern __shared__ char sm[];
    u32 smb = smem_u32(sm);
    int tid = threadIdx.x, wid = tid >> 5, ln = tid & 31;
    int ht = blockIdx.x, c = blockIdx.y, b = blockIdx.z;
    int h0 = ht * HT;
    int mw = (wid >> 2) * 64;
    int nw = (wid & 3) * 32;

    const float* Eg = g_E + ((size_t)b * NL + c * CK) * ND;
    const float* Sg = g_S + (size_t)(b * NCH + c) * CK * CK;
    const float* Mg = g_M + (size_t)(b * NCH + c) * DH + h0;
    const float* Xg = bx  + ((size_t)b * NL + c * CK) * NH + h0;

    float acc[4][4][4];
    #pragma unroll
    for (int i = 0; i < 4; i++)
        #pragma unroll
        for (int j = 0; j < 4; j++)
            #pragma unroll
            for (int k = 0; k < 4; k++) acc[i][j][k] = 0.f;

    for (int slab = 0; slab < 3; slab++) {
        const float *ga, *gb; int gsa;
        if (slab == 0) { ga = Eg;                 gsa = ND; gb = Mg; }
        else           { ga = Sg + (slab - 1)*64; gsa = CK; gb = Xg + (size_t)(slab - 1) * 64 * NH; }
        loadA<128>(sm, KF_AH, KF_AL, ga, gsa, tid);
        loadB(sm, KF_BH, KF_BL, gb, NH, tid);
        __syncthreads();

        #pragma unroll
        for (int ks = 0; ks < 4; ks++) {
            u32 ah[4][4], al[4][4], bh[2][4], bl[2][4];
            #pragma unroll
            for (int mt = 0; mt < 4; mt++) {   // A non-trans: rows=m(j), cols=k
                int row = mw + mt * 16 + (ln & 15);
                int kc = ks * 2 + (ln >> 4);
                u32 off = row * 128 + ((kc ^ (row & 7)) << 4);
                ldsm4(ah[mt], smb + KF_AH + off);
                ldsm4(al[mt], smb + KF_AL + off);
            }
            int q = ln >> 3;
            #pragma unroll
            for (int nt2 = 0; nt2 < 2; nt2++) { // B trans: rows=k, cols=n(h)
                int r = ks * 16 + (q & 1) * 8 + (ln & 7);
                int nc = (nw + nt2 * 16 + (q >> 1) * 8) >> 3;
                u32 off = r * 256 + ((nc ^ (r & 7)) << 4);
                ldsm4t(bh[nt2], smb + KF_BH + off);
                ldsm4t(bl[nt2], smb + KF_BL + off);
            }
            #pragma unroll
            for (int mt = 0; mt < 4; mt++)
                #pragma unroll
                for (int nt2 = 0; nt2 < 2; nt2++) {
                    mma16816(acc[mt][nt2*2],   ah[mt], &bh[nt2][0]);
                    mma16816(acc[mt][nt2*2+1], ah[mt], &bh[nt2][2]);
                    mma16816(acc[mt][nt2*2],   ah[mt], &bl[nt2][0]);
                    mma16816(acc[mt][nt2*2+1], ah[mt], &bl[nt2][2]);
                    mma16816(acc[mt][nt2*2],   al[mt], &bh[nt2][0]);
                    mma16816(acc[mt][nt2*2+1], al[mt], &bh[nt2][2]);
                }
        }
        __syncthreads();
    }

    // Epilogue: out = x + (1/(j+1)) * acc
    #pragma unroll
    for (int mt = 0; mt < 4; mt++)
        #pragma unroll
        for (int half = 0; half < 2; half++) {
            int jl = mw + mt * 16 + (ln >> 2) + half * 8;
            float rj = 1.f / (float)(c * CK + jl + 1);
            size_t base = ((size_t)b * NL + c * CK + jl) * NH + h0 + nw + (ln & 3) * 2;
            #pragma unroll
            for (int nt = 0; nt < 4; nt++) {
                float2 x = *(const float2*)(bx + base + nt * 8);
                *(float2*)(out + base + nt * 8) =
                    make_float2(x.x + rj * acc[mt][nt][half*2],
                                x.y + rj * acc[mt][nt][half*2 + 1]);
            }
        }
}

// ---------------------------------------------------------------------------
extern "C" void kernel_launch(void* const* d_in, const int* in_sizes, int n_in,
                              void* d_out, int out_size)
{
    const float* bx = (const float*)d_in[0];   // bert_x [B,L,H] f32
    const void*  x  = d_in[1];                 // x      [B,L]   int32/int64 (auto)
    const float* ae = (const float*)d_in[2];   // ae     [V,D]   f32
    const float* w  = (const float*)d_in[3];   // w      [D,D]   f32
    float* out = (float*)d_out;

    (void)in_sizes; (void)n_in; (void)out_size;

    cudaFuncSetAttribute(k_outer_mma, cudaFuncAttributeMaxDynamicSharedMemorySize, KO_TOT);
    cudaFuncSetAttribute(k_final_mma, cudaFuncAttributeMaxDynamicSharedMemorySize, KF_TOT);

    k_embed    <<<NB * NL / 4, 256>>>(x, ae, w);
    k_scores   <<<dim3(NCH, NB), 256>>>();
    k_outer_mma<<<dim3(NHT, NCH, NB), 256, KO_TOT>>>(bx);
    k_prefix   <<<NB * DH / 256, 256>>>();
    k_final_mma<<<dim3(NHT, NCH, NB), 256, KF_TOT>>>(bx, out);
}